// round 2
// baseline (speedup 1.0000x reference)
#include <cuda_runtime.h>
#include <math.h>

// Problem constants
#define Bc   64
#define Sc   512
#define Dc   512
#define Hc   8
#define DKc  64
#define Lc   4
#define DFFc 2048
#define NSKc 300
#define FC1c 512
#define FC2c 256
#define Mr   (Bc * Sc)   // 32768 rows

// ---------------- scratch (device globals; no allocations allowed) ----------
__device__ float g_qe[(size_t)Mr * Dc];
__device__ float g_x [(size_t)Mr * Dc];
__device__ float g_y [(size_t)Mr * Dc];
__device__ float g_K [(size_t)Mr * Dc];
__device__ float g_V [(size_t)Mr * Dc];
__device__ float g_O [(size_t)Mr * Dc];
__device__ float g_P [(size_t)Mr * Dc];
__device__ float g_F1[(size_t)Mr * DFFc];
__device__ float g_C [(size_t)Mr * 2 * Dc];
__device__ float g_H1[(size_t)Mr * FC1c];
__device__ float g_H2[(size_t)Mr * FC2c];

// ---------------- embed: qe, x = qe+pe, y = qa_emb[target]+qe+pe ------------
__global__ void embed_kernel(const int* __restrict__ q_data,
                             const int* __restrict__ target,
                             const float* __restrict__ pe,
                             const float* __restrict__ q_emb,
                             const float* __restrict__ qa_emb) {
    size_t idx = (size_t)blockIdx.x * blockDim.x + threadIdx.x;
    if (idx >= (size_t)Mr * Dc) return;
    int bs = (int)(idx / Dc);
    int d  = (int)(idx % Dc);
    int s  = bs % Sc;
    float qe = q_emb[(size_t)q_data[bs] * Dc + d];
    float p  = pe[(size_t)s * Dc + d];
    g_qe[idx] = qe;
    g_x [idx] = qe + p;
    g_y [idx] = qa_emb[(size_t)target[bs] * Dc + d] + qe + p;
}

// ---------------- tiled fp32 GEMM: C = [relu](A @ W + bias) -----------------
// A [M,K] row-major, W [K,N] row-major, C [M,N]. M % 128 == 0, K % 8 == 0.
#define BM 128
#define BN 128
#define BK 8

__global__ __launch_bounds__(256)
void gemm_bias_kernel(const float* __restrict__ A, const float* __restrict__ W,
                      const float* __restrict__ bias, float* __restrict__ C,
                      int M, int K, int N, int relu) {
    __shared__ float As[BK][BM + 4];
    __shared__ float Bs[BK][BN];
    const int tid = threadIdx.x;            // 256 threads
    const int m0 = blockIdx.y * BM;
    const int n0 = blockIdx.x * BN;
    const int tx = tid & 15;                // 0..15 (N dim)
    const int ty = tid >> 4;                // 0..15 (M dim)

    const int ar = tid >> 1;                // A tile row 0..127
    const int ac = (tid & 1) * 4;           // A tile col 0 or 4
    const int bk = tid >> 5;                // B tile row 0..7
    const int bn = (tid & 31) * 4;          // B tile col 0..124
    const bool nfull = (n0 + BN <= N);

    float acc[8][8];
    #pragma unroll
    for (int i = 0; i < 8; i++)
        #pragma unroll
        for (int j = 0; j < 8; j++) acc[i][j] = 0.f;

    for (int k0 = 0; k0 < K; k0 += BK) {
        float4 av = *(const float4*)(A + (size_t)(m0 + ar) * K + k0 + ac);
        As[ac + 0][ar] = av.x;
        As[ac + 1][ar] = av.y;
        As[ac + 2][ar] = av.z;
        As[ac + 3][ar] = av.w;
        if (nfull) {
            *(float4*)&Bs[bk][bn] =
                *(const float4*)(W + (size_t)(k0 + bk) * N + n0 + bn);
        } else {
            #pragma unroll
            for (int j = 0; j < 4; j++) {
                int n = n0 + bn + j;
                Bs[bk][bn + j] = (n < N) ? W[(size_t)(k0 + bk) * N + n] : 0.f;
            }
        }
        __syncthreads();
        #pragma unroll
        for (int kk = 0; kk < BK; kk++) {
            float a[8], b[8];
            #pragma unroll
            for (int i = 0; i < 8; i++) a[i] = As[kk][ty * 8 + i];
            #pragma unroll
            for (int j = 0; j < 8; j++) b[j] = Bs[kk][tx * 8 + j];
            #pragma unroll
            for (int i = 0; i < 8; i++)
                #pragma unroll
                for (int j = 0; j < 8; j++) acc[i][j] += a[i] * b[j];
        }
        __syncthreads();
    }

    #pragma unroll
    for (int i = 0; i < 8; i++) {
        int m = m0 + ty * 8 + i;
        #pragma unroll
        for (int j = 0; j < 8; j++) {
            int n = n0 + tx * 8 + j;
            if (n < N) {
                float v = acc[i][j] + bias[n];
                if (relu) v = fmaxf(v, 0.f);
                C[(size_t)m * N + n] = v;
            }
        }
    }
}

// ---------------- flash attention (Q==K from g_K, V from g_V) ---------------
// strict causal mask (j < i); row i==0 outputs zero (post-softmax row_keep).
// grid: (qtile=8, h=8, b=64), block 256. 4 threads per query row, 16 dims each.
__global__ __launch_bounds__(256)
void attn_kernel() {
    const int qt = blockIdx.x, h = blockIdx.y, b = blockIdx.z;
    const int tid = threadIdx.x;
    const int r = tid >> 2;       // query row within tile 0..63
    const int p = tid & 3;        // dim quarter
    const int i = qt * 64 + r;    // global query position
    const float scale = 0.125f;   // 1/sqrt(64)

    __shared__ float Kt[64][64];
    __shared__ float Vt[64][64];

    float q[16];
    {
        const float* qp = g_K + ((size_t)(b * Sc + i)) * Dc + h * DKc + p * 16;
        #pragma unroll
        for (int w = 0; w < 4; w++) {
            float4 v = *(const float4*)(qp + w * 4);
            q[w * 4 + 0] = v.x; q[w * 4 + 1] = v.y;
            q[w * 4 + 2] = v.z; q[w * 4 + 3] = v.w;
        }
    }

    float m_run = -1e30f, l_run = 0.f;
    float o[16];
    #pragma unroll
    for (int d = 0; d < 16; d++) o[d] = 0.f;

    for (int jt = 0; jt <= qt; jt++) {
        const size_t base = ((size_t)(b * Sc + jt * 64 + r)) * Dc + h * DKc + p * 16;
        #pragma unroll
        for (int w = 0; w < 4; w++) {
            *(float4*)&Kt[r][p * 16 + w * 4] = *(const float4*)(g_K + base + w * 4);
            *(float4*)&Vt[r][p * 16 + w * 4] = *(const float4*)(g_V + base + w * 4);
        }
        __syncthreads();

        // uniform loop (all lanes converged for the shfl reduce); mask per-row
        for (int j = 0; j < 64; j++) {
            float s = 0.f;
            #pragma unroll
            for (int d = 0; d < 16; d++) s += q[d] * Kt[j][p * 16 + d];
            s += __shfl_xor_sync(0xffffffffu, s, 1);
            s += __shfl_xor_sync(0xffffffffu, s, 2);
            s *= scale;
            if (jt * 64 + j < i) {
                float m_new = fmaxf(m_run, s);
                float corr  = __expf(m_run - m_new);
                float pj    = __expf(s - m_new);
                l_run = l_run * corr + pj;
                #pragma unroll
                for (int d = 0; d < 16; d++)
                    o[d] = o[d] * corr + pj * Vt[j][p * 16 + d];
                m_run = m_new;
            }
        }
        __syncthreads();
    }

    float inv = (l_run > 0.f) ? (1.f / l_run) : 0.f;
    float* op = g_O + ((size_t)(b * Sc + i)) * Dc + h * DKc + p * 16;
    #pragma unroll
    for (int d = 0; d < 16; d++) op[d] = o[d] * inv;
}

// ---------------- fused residual add + LayerNorm (in-place on x) ------------
__global__ __launch_bounds__(256)
void add_ln_kernel(float* __restrict__ x, const float* __restrict__ resid,
                   const float* __restrict__ g, const float* __restrict__ b) {
    const int row = blockIdx.x;
    const int tid = threadIdx.x;    // 256, 2 elems each
    const size_t base = (size_t)row * Dc;
    float v0 = x[base + tid]       + resid[base + tid];
    float v1 = x[base + tid + 256] + resid[base + tid + 256];
    float s  = v0 + v1;
    float ss = v0 * v0 + v1 * v1;

    __shared__ float sbuf[8], ssbuf[8];
    #pragma unroll
    for (int o = 16; o > 0; o >>= 1) {
        s  += __shfl_xor_sync(0xffffffffu, s, o);
        ss += __shfl_xor_sync(0xffffffffu, ss, o);
    }
    if ((tid & 31) == 0) { sbuf[tid >> 5] = s; ssbuf[tid >> 5] = ss; }
    __syncthreads();
    if (tid < 32) {
        s  = (tid < 8) ? sbuf[tid]  : 0.f;
        ss = (tid < 8) ? ssbuf[tid] : 0.f;
        #pragma unroll
        for (int o = 4; o > 0; o >>= 1) {
            s  += __shfl_xor_sync(0xffffffffu, s, o);
            ss += __shfl_xor_sync(0xffffffffu, ss, o);
        }
        if (tid == 0) { sbuf[0] = s; ssbuf[0] = ss; }
    }
    __syncthreads();
    float mean = sbuf[0] * (1.f / 512.f);
    float var  = ssbuf[0] * (1.f / 512.f) - mean * mean;
    float rstd = rsqrtf(var + 1e-5f);
    x[base + tid]       = (v0 - mean) * rstd * g[tid]       + b[tid];
    x[base + tid + 256] = (v1 - mean) * rstd * g[tid + 256] + b[tid + 256];
}

// ---------------- concat [x | qe] -------------------------------------------
__global__ void concat_kernel() {
    size_t idx = (size_t)blockIdx.x * blockDim.x + threadIdx.x;
    if (idx >= (size_t)Mr * 2 * Dc) return;
    int bs = (int)(idx / (2 * Dc));
    int c  = (int)(idx % (2 * Dc));
    g_C[idx] = (c < Dc) ? g_x[(size_t)bs * Dc + c]
                        : g_qe[(size_t)bs * Dc + (c - Dc)];
}

// ---------------- launch ----------------------------------------------------
static inline void gemm(const float* A, const float* W, const float* bias,
                        float* C, int M, int K, int N, int relu) {
    dim3 grid((N + BN - 1) / BN, M / BM);
    gemm_bias_kernel<<<grid, 256>>>(A, W, bias, C, M, K, N, relu);
}

extern "C" void kernel_launch(void* const* d_in, const int* in_sizes, int n_in,
                              void* d_out, int out_size) {
    const int*   q_data = (const int*)d_in[0];
    const int*   target = (const int*)d_in[1];
    const float* pe     = (const float*)d_in[2];
    const float* q_emb  = (const float*)d_in[3];
    const float* qa_emb = (const float*)d_in[4];
    const float* Wk     = (const float*)d_in[5];
    const float* bk     = (const float*)d_in[6];
    const float* Wv     = (const float*)d_in[7];
    const float* bv     = (const float*)d_in[8];
    const float* Wo     = (const float*)d_in[9];
    const float* bo     = (const float*)d_in[10];
    const float* ln1_g  = (const float*)d_in[11];
    const float* ln1_b  = (const float*)d_in[12];
    const float* W1     = (const float*)d_in[13];
    const float* b1     = (const float*)d_in[14];
    const float* W2     = (const float*)d_in[15];
    const float* b2     = (const float*)d_in[16];
    const float* ln2_g  = (const float*)d_in[17];
    const float* ln2_b  = (const float*)d_in[18];
    const float* Wout1  = (const float*)d_in[19];
    const float* bout1  = (const float*)d_in[20];
    const float* Wout2  = (const float*)d_in[21];
    const float* bout2  = (const float*)d_in[22];
    const float* Wout3  = (const float*)d_in[23];
    const float* bout3  = (const float*)d_in[24];
    float* out = (float*)d_out;

    float *p_qe, *p_x, *p_y, *p_K, *p_V, *p_O, *p_P, *p_F1, *p_C, *p_H1, *p_H2;
    cudaGetSymbolAddress((void**)&p_qe, g_qe);
    cudaGetSymbolAddress((void**)&p_x,  g_x);
    cudaGetSymbolAddress((void**)&p_y,  g_y);
    cudaGetSymbolAddress((void**)&p_K,  g_K);
    cudaGetSymbolAddress((void**)&p_V,  g_V);
    cudaGetSymbolAddress((void**)&p_O,  g_O);
    cudaGetSymbolAddress((void**)&p_P,  g_P);
    cudaGetSymbolAddress((void**)&p_F1, g_F1);
    cudaGetSymbolAddress((void**)&p_C,  g_C);
    cudaGetSymbolAddress((void**)&p_H1, g_H1);
    cudaGetSymbolAddress((void**)&p_H2, g_H2);

    const int M = Mr;

    // embed
    {
        size_t tot = (size_t)Mr * Dc;
        embed_kernel<<<(unsigned)((tot + 255) / 256), 256>>>(q_data, target, pe, q_emb, qa_emb);
    }

    for (int l = 0; l < Lc; l++) {
        const float* Wk_l = Wk + (size_t)l * Dc * Dc;
        const float* Wv_l = Wv + (size_t)l * Dc * Dc;
        const float* Wo_l = Wo + (size_t)l * Dc * Dc;
        const float* W1_l = W1 + (size_t)l * Dc * DFFc;
        const float* W2_l = W2 + (size_t)l * DFFc * Dc;

        gemm(p_x, Wk_l, bk + l * Dc, p_K, M, Dc, Dc, 0);   // K (== Q)
        gemm(p_y, Wv_l, bv + l * Dc, p_V, M, Dc, Dc, 0);   // V
        attn_kernel<<<dim3(Sc / 64, Hc, Bc), 256>>>();      // flash attention -> g_O
        gemm(p_O, Wo_l, bo + l * Dc, p_P, M, Dc, Dc, 0);   // output proj
        add_ln_kernel<<<M, 256>>>(p_x, p_P, ln1_g + l * Dc, ln1_b + l * Dc);
        gemm(p_x, W1_l, b1 + l * DFFc, p_F1, M, Dc, DFFc, 1);   // FFN up + relu
        gemm(p_F1, W2_l, b2 + l * Dc, p_P, M, DFFc, Dc, 0);     // FFN down
        add_ln_kernel<<<M, 256>>>(p_x, p_P, ln2_g + l * Dc, ln2_b + l * Dc);
    }

    // head
    {
        size_t tot = (size_t)Mr * 2 * Dc;
        concat_kernel<<<(unsigned)((tot + 255) / 256), 256>>>();
    }
    gemm(p_C,  Wout1, bout1, p_H1, M, 2 * Dc, FC1c, 1);
    gemm(p_H1, Wout2, bout2, p_H2, M, FC1c, FC2c, 1);
    gemm(p_H2, Wout3, bout3, out, M, FC2c, NSKc, 0);
}

// round 4
// speedup vs baseline: 1.9242x; 1.9242x over previous
#include <cuda_runtime.h>
#include <cuda_fp16.h>
#include <math.h>
#include <stdint.h>

#define Bc   64
#define Sc   512
#define Dc   512
#define Hc   8
#define DKc  64
#define Lc   4
#define DFFc 2048
#define NSKc 300
#define NSKp 384
#define FC1c 512
#define FC2c 256
#define Mr   (Bc * Sc)

// ---------------- scratch ----------------
__device__ float g_qe[(size_t)Mr * Dc];
__device__ float g_x [(size_t)Mr * Dc];
__device__ float g_y [(size_t)Mr * Dc];
__device__ float g_K [(size_t)Mr * Dc];
__device__ float g_V [(size_t)Mr * Dc];
__device__ float g_O [(size_t)Mr * Dc];
__device__ float g_P [(size_t)Mr * Dc];
__device__ float g_F1[(size_t)Mr * DFFc];
__device__ float g_C [(size_t)Mr * 2 * Dc];
__device__ float g_H1[(size_t)Mr * FC1c];
__device__ float g_H2[(size_t)Mr * FC2c];

__device__ __half g_Wk_h[(size_t)Lc * Dc * Dc],   g_Wk_l[(size_t)Lc * Dc * Dc];
__device__ __half g_Wv_h[(size_t)Lc * Dc * Dc],   g_Wv_l[(size_t)Lc * Dc * Dc];
__device__ __half g_Wo_h[(size_t)Lc * Dc * Dc],   g_Wo_l[(size_t)Lc * Dc * Dc];
__device__ __half g_W1_h[(size_t)Lc * Dc * DFFc], g_W1_l[(size_t)Lc * Dc * DFFc];
__device__ __half g_W2_h[(size_t)Lc * DFFc * Dc], g_W2_l[(size_t)Lc * DFFc * Dc];
__device__ __half g_Wo1_h[(size_t)2 * Dc * FC1c], g_Wo1_l[(size_t)2 * Dc * FC1c];
__device__ __half g_Wo2_h[(size_t)FC1c * FC2c],   g_Wo2_l[(size_t)FC1c * FC2c];
__device__ __half g_Wo3_h[(size_t)NSKp * FC2c],   g_Wo3_l[(size_t)NSKp * FC2c];

// ---------------- helpers ----------------
__device__ __forceinline__ uint32_t smem_u32(const void* p) {
    uint32_t a;
    asm("{ .reg .u64 t; cvta.to.shared.u64 t, %1; cvt.u32.u64 %0, t; }"
        : "=r"(a) : "l"(p));
    return a;
}

#define LDMX4(R, addr)                                                        \
    asm volatile("ldmatrix.sync.aligned.m8n8.x4.shared.b16 {%0,%1,%2,%3}, [%4];" \
        : "=r"((R)[0]), "=r"((R)[1]), "=r"((R)[2]), "=r"((R)[3]) : "r"(addr))

#define LDMX2(R, addr)                                                        \
    asm volatile("ldmatrix.sync.aligned.m8n8.x2.shared.b16 {%0,%1}, [%2];"    \
        : "=r"((R)[0]), "=r"((R)[1]) : "r"(addr))

#define MMA16816(d, a, b)                                                     \
    asm volatile("mma.sync.aligned.m16n8k16.row.col.f32.f16.f16.f32 "         \
        "{%0,%1,%2,%3}, {%4,%5,%6,%7}, {%8,%9}, {%0,%1,%2,%3};"               \
        : "+f"((d)[0]), "+f"((d)[1]), "+f"((d)[2]), "+f"((d)[3])              \
        : "r"((a)[0]), "r"((a)[1]), "r"((a)[2]), "r"((a)[3]),                 \
          "r"((b)[0]), "r"((b)[1]))

// ---------------- weight prep: transpose + hi/lo split ----------------
__global__ void split_w_kernel(const float* __restrict__ W,
                               __half* __restrict__ Oh, __half* __restrict__ Ol,
                               int K, int N) {
    __shared__ float t[32][33];
    int k0 = blockIdx.y * 32, n0 = blockIdx.x * 32;
    #pragma unroll
    for (int i = 0; i < 4; i++) {
        int k = k0 + threadIdx.y + i * 8;
        int n = n0 + threadIdx.x;
        t[threadIdx.y + i * 8][threadIdx.x] = (n < N) ? W[(size_t)k * N + n] : 0.f;
    }
    __syncthreads();
    #pragma unroll
    for (int i = 0; i < 4; i++) {
        int n = n0 + threadIdx.y + i * 8;
        int k = k0 + threadIdx.x;
        float v = t[threadIdx.x][threadIdx.y + i * 8];
        __half h = __float2half_rn(v);
        __half l = __float2half_rn(v - __half2float(h));
        Oh[(size_t)n * K + k] = h;
        Ol[(size_t)n * K + k] = l;
    }
}

// ---------------- split-fp16 mma.sync GEMM ----------------
// C[M,N] = [relu](A[M,K] @ W + bias), W pre-split hi/lo fp16 stored [Npad][K].
// CTA 128x128, BK=32, 8 warps (2m x 4n), warp tile 64x32, 2-stage pipeline.
#define APITCH 40                 // halfs per smem row (32 + 8 pad)
#define STAGE_B 40960             // 4 tiles * 128*40*2 bytes
#define GEMM_DSMEM (2 * STAGE_B)  // 81920

__global__ __launch_bounds__(256, 1)
void gemm_mma_kernel(const float* __restrict__ A,
                     const __half* __restrict__ Bh_g,
                     const __half* __restrict__ Bl_g,
                     const float* __restrict__ bias,
                     float* __restrict__ C,
                     int K, int N, int relu) {
    extern __shared__ char smem[];
    const int tid  = threadIdx.x;
    const int wid  = tid >> 5;
    const int lane = tid & 31;
    const int m0 = blockIdx.y * 128;
    const int n0 = blockIdx.x * 128;
    const int warp_m = (wid >> 2) * 64;   // 0 / 64
    const int warp_n = (wid & 3) * 32;    // 0 / 32 / 64 / 96

    const uint32_t sbase = smem_u32(smem);

    float acc[4][4][4];
    #pragma unroll
    for (int i = 0; i < 4; i++)
        #pragma unroll
        for (int j = 0; j < 4; j++)
            #pragma unroll
            for (int e = 0; e < 4; e++) acc[i][j][e] = 0.f;

    float a_stage[16];
    uint4 bh_stage[2], bl_stage[2];

    const int KT = K >> 5;  // K / 32

    // per-lane ldmatrix offsets
    const int r8  = lane & 7;
    const int sub = lane >> 3;
    const uint32_t a_lane_off =
        (uint32_t)(((warp_m + r8 + (sub & 1) * 8) * APITCH + (sub >> 1) * 8) * 2);
    const uint32_t b_lane_off =
        (uint32_t)(((warp_n + r8) * APITCH + (sub & 1) * 8) * 2);

    // ---- gmem load of tile kt into registers ----
    #define LOADG(kt) do {                                                    \
        const int kk = (kt) << 5;                                             \
        _Pragma("unroll")                                                     \
        for (int p = 0; p < 4; p++) {                                         \
            int idx = p * 256 + tid; int row = idx >> 3; int q = idx & 7;     \
            *(float4*)&a_stage[p * 4] =                                       \
                *(const float4*)(A + (size_t)(m0 + row) * K + kk + q * 4);    \
        }                                                                     \
        _Pragma("unroll")                                                     \
        for (int p = 0; p < 2; p++) {                                         \
            int idx = p * 256 + tid; int row = idx >> 2; int q = idx & 3;     \
            size_t go = (size_t)(n0 + row) * K + kk + q * 8;                  \
            bh_stage[p] = *(const uint4*)(Bh_g + go);                         \
            bl_stage[p] = *(const uint4*)(Bl_g + go);                         \
        }                                                                     \
    } while (0)

    // ---- store staged registers into smem stage st ----
    #define STORES(st) do {                                                   \
        char* sb = smem + (st) * STAGE_B;                                     \
        _Pragma("unroll")                                                     \
        for (int p = 0; p < 4; p++) {                                         \
            int idx = p * 256 + tid; int row = idx >> 3; int q = idx & 7;     \
            float vx = a_stage[p*4+0], vy = a_stage[p*4+1];                   \
            float vz = a_stage[p*4+2], vw = a_stage[p*4+3];                   \
            __half hx = __float2half_rn(vx), hy = __float2half_rn(vy);        \
            __half hz = __float2half_rn(vz), hw = __float2half_rn(vw);        \
            __half lx = __float2half_rn(vx - __half2float(hx));               \
            __half ly = __float2half_rn(vy - __half2float(hy));               \
            __half lz = __float2half_rn(vz - __half2float(hz));               \
            __half lw = __float2half_rn(vw - __half2float(hw));               \
            uint32_t h01 = (uint32_t)__half_as_ushort(hx) |                   \
                           ((uint32_t)__half_as_ushort(hy) << 16);            \
            uint32_t h23 = (uint32_t)__half_as_ushort(hz) |                   \
                           ((uint32_t)__half_as_ushort(hw) << 16);            \
            uint32_t l01 = (uint32_t)__half_as_ushort(lx) |                   \
                           ((uint32_t)__half_as_ushort(ly) << 16);            \
            uint32_t l23 = (uint32_t)__half_as_ushort(lz) |                   \
                           ((uint32_t)__half_as_ushort(lw) << 16);            \
            uint32_t off = (uint32_t)((row * APITCH + q * 4) * 2);            \
            *(uint2*)(sb + off)         = make_uint2(h01, h23);               \
            *(uint2*)(sb + 10240 + off) = make_uint2(l01, l23);               \
        }                                                                     \
        _Pragma("unroll")                                                     \
        for (int p = 0; p < 2; p++) {                                         \
            int idx = p * 256 + tid; int row = idx >> 2; int q = idx & 3;     \
            uint32_t off = (uint32_t)((row * APITCH + q * 8) * 2);            \
            *(uint4*)(sb + 20480 + off) = bh_stage[p];                        \
            *(uint4*)(sb + 30720 + off) = bl_stage[p];                        \
        }                                                                     \
    } while (0)

    LOADG(0);
    STORES(0);

    for (int kt = 0; kt < KT; kt++) {
        __syncthreads();
        const int st = kt & 1;
        const bool more = (kt + 1 < KT);
        if (more) LOADG(kt + 1);

        const uint32_t abase = sbase + st * STAGE_B + a_lane_off;
        const uint32_t bbase = sbase + st * STAGE_B + 20480 + b_lane_off;

        #pragma unroll
        for (int ks = 0; ks < 2; ks++) {
            const uint32_t ak = abase + ks * 32;  // 16 halfs = 32 bytes
            const uint32_t bk = bbase + ks * 32;

            uint32_t Ahf[4][4], Bhf[4][2];
            #pragma unroll
            for (int fi = 0; fi < 4; fi++)
                LDMX4(Ahf[fi], ak + fi * (16 * APITCH * 2));
            #pragma unroll
            for (int fj = 0; fj < 4; fj++)
                LDMX2(Bhf[fj], bk + fj * (8 * APITCH * 2));
            #pragma unroll
            for (int fi = 0; fi < 4; fi++)
                #pragma unroll
                for (int fj = 0; fj < 4; fj++)
                    MMA16816(acc[fi][fj], Ahf[fi], Bhf[fj]);

            uint32_t Blf[4][2];
            #pragma unroll
            for (int fj = 0; fj < 4; fj++)
                LDMX2(Blf[fj], bk + 10240 + fj * (8 * APITCH * 2));
            #pragma unroll
            for (int fi = 0; fi < 4; fi++)
                #pragma unroll
                for (int fj = 0; fj < 4; fj++)
                    MMA16816(acc[fi][fj], Ahf[fi], Blf[fj]);

            uint32_t Alf[4][4];
            #pragma unroll
            for (int fi = 0; fi < 4; fi++)
                LDMX4(Alf[fi], ak + 10240 + fi * (16 * APITCH * 2));
            #pragma unroll
            for (int fi = 0; fi < 4; fi++)
                #pragma unroll
                for (int fj = 0; fj < 4; fj++)
                    MMA16816(acc[fi][fj], Alf[fi], Bhf[fj]);
        }

        if (more) STORES((kt + 1) & 1);
    }

    // ---- epilogue: registers -> gmem with bias/relu ----
    #pragma unroll
    for (int fj = 0; fj < 4; fj++) {
        const int c0 = n0 + warp_n + fj * 8 + 2 * (lane & 3);
        const bool c0ok = (c0 < N), c1ok = (c0 + 1 < N);
        const float b0 = c0ok ? bias[c0] : 0.f;
        const float b1 = c1ok ? bias[c0 + 1] : 0.f;
        #pragma unroll
        for (int fi = 0; fi < 4; fi++) {
            const int r0 = m0 + warp_m + fi * 16 + (lane >> 2);
            float v0 = acc[fi][fj][0] + b0;
            float v1 = acc[fi][fj][1] + b1;
            float v2 = acc[fi][fj][2] + b0;
            float v3 = acc[fi][fj][3] + b1;
            if (relu) {
                v0 = fmaxf(v0, 0.f); v1 = fmaxf(v1, 0.f);
                v2 = fmaxf(v2, 0.f); v3 = fmaxf(v3, 0.f);
            }
            if (c0ok) {
                C[(size_t)r0 * N + c0]       = v0;
                C[(size_t)(r0 + 8) * N + c0] = v2;
            }
            if (c1ok) {
                C[(size_t)r0 * N + c0 + 1]       = v1;
                C[(size_t)(r0 + 8) * N + c0 + 1] = v3;
            }
        }
    }
    #undef LOADG
    #undef STORES
}

// ---------------- embed ----------------
__global__ void embed_kernel(const int* __restrict__ q_data,
                             const int* __restrict__ target,
                             const float* __restrict__ pe,
                             const float* __restrict__ q_emb,
                             const float* __restrict__ qa_emb) {
    size_t idx = (size_t)blockIdx.x * blockDim.x + threadIdx.x;
    if (idx >= (size_t)Mr * Dc) return;
    int bs = (int)(idx / Dc);
    int d  = (int)(idx % Dc);
    int s  = bs % Sc;
    float qe = q_emb[(size_t)q_data[bs] * Dc + d];
    float p  = pe[(size_t)s * Dc + d];
    g_qe[idx] = qe;
    g_x [idx] = qe + p;
    g_y [idx] = qa_emb[(size_t)target[bs] * Dc + d] + qe + p;
}

// ---------------- flash attention ----------------
__global__ __launch_bounds__(256)
void attn_kernel() {
    const int qt = blockIdx.x, h = blockIdx.y, b = blockIdx.z;
    const int tid = threadIdx.x;
    const int r = tid >> 2;
    const int p = tid & 3;
    const int i = qt * 64 + r;
    const float scale = 0.125f;

    __shared__ float Kt[64][64];
    __shared__ float Vt[64][64];

    float q[16];
    {
        const float* qp = g_K + ((size_t)(b * Sc + i)) * Dc + h * DKc + p * 16;
        #pragma unroll
        for (int w = 0; w < 4; w++) {
            float4 v = *(const float4*)(qp + w * 4);
            q[w * 4 + 0] = v.x; q[w * 4 + 1] = v.y;
            q[w * 4 + 2] = v.z; q[w * 4 + 3] = v.w;
        }
    }

    float m_run = -1e30f, l_run = 0.f;
    float o[16];
    #pragma unroll
    for (int d = 0; d < 16; d++) o[d] = 0.f;

    for (int jt = 0; jt <= qt; jt++) {
        const size_t base = ((size_t)(b * Sc + jt * 64 + r)) * Dc + h * DKc + p * 16;
        #pragma unroll
        for (int w = 0; w < 4; w++) {
            *(float4*)&Kt[r][p * 16 + w * 4] = *(const float4*)(g_K + base + w * 4);
            *(float4*)&Vt[r][p * 16 + w * 4] = *(const float4*)(g_V + base + w * 4);
        }
        __syncthreads();

        for (int j = 0; j < 64; j++) {
            float s = 0.f;
            #pragma unroll
            for (int d = 0; d < 16; d++) s += q[d] * Kt[j][p * 16 + d];
            s += __shfl_xor_sync(0xffffffffu, s, 1);
            s += __shfl_xor_sync(0xffffffffu, s, 2);
            s *= scale;
            if (jt * 64 + j < i) {
                float m_new = fmaxf(m_run, s);
                float corr  = __expf(m_run - m_new);
                float pj    = __expf(s - m_new);
                l_run = l_run * corr + pj;
                #pragma unroll
                for (int d = 0; d < 16; d++)
                    o[d] = o[d] * corr + pj * Vt[j][p * 16 + d];
                m_run = m_new;
            }
        }
        __syncthreads();
    }

    float inv = (l_run > 0.f) ? (1.f / l_run) : 0.f;
    float* op = g_O + ((size_t)(b * Sc + i)) * Dc + h * DKc + p * 16;
    #pragma unroll
    for (int d = 0; d < 16; d++) op[d] = o[d] * inv;
}

// ---------------- fused add + LayerNorm ----------------
__global__ __launch_bounds__(256)
void add_ln_kernel(float* __restrict__ x, const float* __restrict__ resid,
                   const float* __restrict__ g, const float* __restrict__ b) {
    const int row = blockIdx.x;
    const int tid = threadIdx.x;
    const size_t base = (size_t)row * Dc;
    float v0 = x[base + tid]       + resid[base + tid];
    float v1 = x[base + tid + 256] + resid[base + tid + 256];
    float s  = v0 + v1;
    float ss = v0 * v0 + v1 * v1;

    __shared__ float sbuf[8], ssbuf[8];
    #pragma unroll
    for (int o = 16; o > 0; o >>= 1) {
        s  += __shfl_xor_sync(0xffffffffu, s, o);
        ss += __shfl_xor_sync(0xffffffffu, ss, o);
    }
    if ((tid & 31) == 0) { sbuf[tid >> 5] = s; ssbuf[tid >> 5] = ss; }
    __syncthreads();
    if (tid < 32) {
        s  = (tid < 8) ? sbuf[tid]  : 0.f;
        ss = (tid < 8) ? ssbuf[tid] : 0.f;
        #pragma unroll
        for (int o = 4; o > 0; o >>= 1) {
            s  += __shfl_xor_sync(0xffffffffu, s, o);
            ss += __shfl_xor_sync(0xffffffffu, ss, o);
        }
        if (tid == 0) { sbuf[0] = s; ssbuf[0] = ss; }
    }
    __syncthreads();
    float mean = sbuf[0] * (1.f / 512.f);
    float var  = ssbuf[0] * (1.f / 512.f) - mean * mean;
    float rstd = rsqrtf(var + 1e-5f);
    x[base + tid]       = (v0 - mean) * rstd * g[tid]       + b[tid];
    x[base + tid + 256] = (v1 - mean) * rstd * g[tid + 256] + b[tid + 256];
}

// ---------------- concat ----------------
__global__ void concat_kernel() {
    size_t idx = (size_t)blockIdx.x * blockDim.x + threadIdx.x;
    if (idx >= (size_t)Mr * 2 * Dc) return;
    int bs = (int)(idx / (2 * Dc));
    int c  = (int)(idx % (2 * Dc));
    g_C[idx] = (c < Dc) ? g_x[(size_t)bs * Dc + c]
                        : g_qe[(size_t)bs * Dc + (c - Dc)];
}

// ---------------- host ----------------
static inline void split_w(const float* W, __half* oh, __half* ol,
                           int K, int N, int Npad) {
    split_w_kernel<<<dim3(Npad / 32, K / 32), dim3(32, 8)>>>(W, oh, ol, K, N);
}
static inline void gemmMMA(const float* A, const __half* bh, const __half* bl,
                           const float* bias, float* C, int K, int N, int Npad,
                           int relu) {
    gemm_mma_kernel<<<dim3(Npad / 128, Mr / 128), 256, GEMM_DSMEM>>>(
        A, bh, bl, bias, C, K, N, relu);
}

extern "C" void kernel_launch(void* const* d_in, const int* in_sizes, int n_in,
                              void* d_out, int out_size) {
    const int*   q_data = (const int*)d_in[0];
    const int*   target = (const int*)d_in[1];
    const float* pe     = (const float*)d_in[2];
    const float* q_emb  = (const float*)d_in[3];
    const float* qa_emb = (const float*)d_in[4];
    const float* Wk     = (const float*)d_in[5];
    const float* bk     = (const float*)d_in[6];
    const float* Wv     = (const float*)d_in[7];
    const float* bv     = (const float*)d_in[8];
    const float* Wo     = (const float*)d_in[9];
    const float* bo     = (const float*)d_in[10];
    const float* ln1_g  = (const float*)d_in[11];
    const float* ln1_b  = (const float*)d_in[12];
    const float* W1     = (const float*)d_in[13];
    const float* b1     = (const float*)d_in[14];
    const float* W2     = (const float*)d_in[15];
    const float* b2     = (const float*)d_in[16];
    const float* ln2_g  = (const float*)d_in[17];
    const float* ln2_b  = (const float*)d_in[18];
    const float* Wout1  = (const float*)d_in[19];
    const float* bout1  = (const float*)d_in[20];
    const float* Wout2  = (const float*)d_in[21];
    const float* bout2  = (const float*)d_in[22];
    const float* Wout3  = (const float*)d_in[23];
    const float* bout3  = (const float*)d_in[24];
    float* out = (float*)d_out;

    cudaFuncSetAttribute(gemm_mma_kernel,
                         cudaFuncAttributeMaxDynamicSharedMemorySize, GEMM_DSMEM);

    float *p_qe, *p_x, *p_y, *p_K, *p_V, *p_O, *p_P, *p_F1, *p_C, *p_H1, *p_H2;
    cudaGetSymbolAddress((void**)&p_qe, g_qe);
    cudaGetSymbolAddress((void**)&p_x,  g_x);
    cudaGetSymbolAddress((void**)&p_y,  g_y);
    cudaGetSymbolAddress((void**)&p_K,  g_K);
    cudaGetSymbolAddress((void**)&p_V,  g_V);
    cudaGetSymbolAddress((void**)&p_O,  g_O);
    cudaGetSymbolAddress((void**)&p_P,  g_P);
    cudaGetSymbolAddress((void**)&p_F1, g_F1);
    cudaGetSymbolAddress((void**)&p_C,  g_C);
    cudaGetSymbolAddress((void**)&p_H1, g_H1);
    cudaGetSymbolAddress((void**)&p_H2, g_H2);

    __half *wk_h, *wk_l, *wv_h, *wv_l, *wo_h, *wo_l, *w1_h, *w1_l, *w2_h, *w2_l;
    __half *wo1_h, *wo1_l, *wo2_h, *wo2_l, *wo3_h, *wo3_l;
    cudaGetSymbolAddress((void**)&wk_h, g_Wk_h); cudaGetSymbolAddress((void**)&wk_l, g_Wk_l);
    cudaGetSymbolAddress((void**)&wv_h, g_Wv_h); cudaGetSymbolAddress((void**)&wv_l, g_Wv_l);
    cudaGetSymbolAddress((void**)&wo_h, g_Wo_h); cudaGetSymbolAddress((void**)&wo_l, g_Wo_l);
    cudaGetSymbolAddress((void**)&w1_h, g_W1_h); cudaGetSymbolAddress((void**)&w1_l, g_W1_l);
    cudaGetSymbolAddress((void**)&w2_h, g_W2_h); cudaGetSymbolAddress((void**)&w2_l, g_W2_l);
    cudaGetSymbolAddress((void**)&wo1_h, g_Wo1_h); cudaGetSymbolAddress((void**)&wo1_l, g_Wo1_l);
    cudaGetSymbolAddress((void**)&wo2_h, g_Wo2_h); cudaGetSymbolAddress((void**)&wo2_l, g_Wo2_l);
    cudaGetSymbolAddress((void**)&wo3_h, g_Wo3_h); cudaGetSymbolAddress((void**)&wo3_l, g_Wo3_l);

    // weight prep (transpose + hi/lo fp16 split)
    for (int l = 0; l < Lc; l++) {
        size_t oDD = (size_t)l * Dc * Dc;
        size_t oDF = (size_t)l * Dc * DFFc;
        split_w(Wk + oDD, wk_h + oDD, wk_l + oDD, Dc, Dc, Dc);
        split_w(Wv + oDD, wv_h + oDD, wv_l + oDD, Dc, Dc, Dc);
        split_w(Wo + oDD, wo_h + oDD, wo_l + oDD, Dc, Dc, Dc);
        split_w(W1 + oDF, w1_h + oDF, w1_l + oDF, Dc, DFFc, DFFc);
        split_w(W2 + oDF, w2_h + oDF, w2_l + oDF, DFFc, Dc, Dc);
    }
    split_w(Wout1, wo1_h, wo1_l, 2 * Dc, FC1c, FC1c);
    split_w(Wout2, wo2_h, wo2_l, FC1c, FC2c, FC2c);
    split_w(Wout3, wo3_h, wo3_l, FC2c, NSKc, NSKp);

    // embed
    {
        size_t tot = (size_t)Mr * Dc;
        embed_kernel<<<(unsigned)((tot + 255) / 256), 256>>>(q_data, target, pe,
                                                             q_emb, qa_emb);
    }

    // transformer layers
    for (int l = 0; l < Lc; l++) {
        size_t oDD = (size_t)l * Dc * Dc;
        size_t oDF = (size_t)l * Dc * DFFc;
        gemmMMA(p_x, wk_h + oDD, wk_l + oDD, bk + l * Dc, p_K, Dc, Dc, Dc, 0);
        gemmMMA(p_y, wv_h + oDD, wv_l + oDD, bv + l * Dc, p_V, Dc, Dc, Dc, 0);
        attn_kernel<<<dim3(Sc / 64, Hc, Bc), 256>>>();
        gemmMMA(p_O, wo_h + oDD, wo_l + oDD, bo + l * Dc, p_P, Dc, Dc, Dc, 0);
        add_ln_kernel<<<Mr, 256>>>(p_x, p_P, ln1_g + l * Dc, ln1_b + l * Dc);
        gemmMMA(p_x, w1_h + oDF, w1_l + oDF, b1 + l * DFFc, p_F1, Dc, DFFc, DFFc, 1);
        gemmMMA(p_F1, w2_h + oDF, w2_l + oDF, b2 + l * Dc, p_P, DFFc, Dc, Dc, 0);
        add_ln_kernel<<<Mr, 256>>>(p_x, p_P, ln2_g + l * Dc, ln2_b + l * Dc);
    }

    // head
    {
        size_t tot = (size_t)Mr * 2 * Dc;
        concat_kernel<<<(unsigned)((tot + 255) / 256), 256>>>();
    }
    gemmMMA(p_C,  wo1_h, wo1_l, bout1, p_H1, 2 * Dc, FC1c, FC1c, 1);
    gemmMMA(p_H1, wo2_h, wo2_l, bout2, p_H2, FC1c, FC2c, FC2c, 1);
    gemmMMA(p_H2, wo3_h, wo3_l, bout3, out, FC2c, NSKc, NSKp, 0);
}